// round 11
// baseline (speedup 1.0000x reference)
#include <cuda_runtime.h>
#include <cuda_fp16.h>
#include <cstdint>
#include <math.h>

#define NMAX 20000
#define EMAX 320000
#define D 512

// ---------------- scratch (static device globals; no allocation) -------------
__device__ float  g_H  [NMAX * D];
__device__ float  g_F  [NMAX * D];
__device__ __half g_H16[NMAX * D];
__device__ __half g_R16[NMAX * D];
__device__ float  g_WB [5 * D * D];     // tf32-rounded weights, ALL [N][K] K-major
__device__ float  g_norm[NMAX];
__device__ int    g_cnt [NMAX];
__device__ int    g_off [NMAX + 1];
__device__ int    g_cur [NMAX + 1];
__device__ int    g_csr [EMAX];

// ================= small helpers ==============================================
__device__ __forceinline__ unsigned f2tf(float x)
{
    unsigned r;
    asm("cvt.rna.tf32.f32 %0, %1;" : "=r"(r) : "f"(x));
    return r;
}
__device__ __forceinline__ float rndtf(float x) { return __uint_as_float(f2tf(x)); }

__device__ __forceinline__ void cp16(uint32_t dst, const float* src, int bytes)
{
    asm volatile("cp.async.cg.shared.global [%0], [%1], 16, %2;"
                 :: "r"(dst), "l"(src), "r"(bytes));
}
__device__ __forceinline__ void cp_commit() { asm volatile("cp.async.commit_group;"); }
template <int N> __device__ __forceinline__ void cp_wait()
{ asm volatile("cp.async.wait_group %0;" :: "n"(N)); }

__device__ __forceinline__ void mma8(float* c,
                                     unsigned a0, unsigned a1, unsigned a2, unsigned a3,
                                     unsigned b0, unsigned b1)
{
    asm volatile(
        "mma.sync.aligned.m16n8k8.row.col.f32.tf32.tf32.f32 "
        "{%0,%1,%2,%3},{%4,%5,%6,%7},{%8,%9},{%0,%1,%2,%3};"
        : "+f"(c[0]), "+f"(c[1]), "+f"(c[2]), "+f"(c[3])
        : "r"(a0), "r"(a1), "r"(a2), "r"(a3), "r"(b0), "r"(b1));
}

__device__ __forceinline__ void ldsm4(unsigned& r0, unsigned& r1, unsigned& r2, unsigned& r3,
                                      uint32_t addr)
{
    asm volatile("ldmatrix.sync.aligned.m8n8.x4.shared.b16 {%0,%1,%2,%3}, [%4];"
                 : "=r"(r0), "=r"(r1), "=r"(r2), "=r"(r3) : "r"(addr));
}

// ================= weight prep ===============================================
__global__ void prep_fc(const float* __restrict__ fcw, float* __restrict__ wb)
{
    int i = blockIdx.x * blockDim.x + threadIdx.x;
    if (i < D * D) wb[i] = rndtf(fcw[i]);
}

__global__ void prep_wT(const float* __restrict__ w11, const float* __restrict__ w21,
                        const float* __restrict__ w12, const float* __restrict__ w22,
                        float* __restrict__ wb)
{
    __shared__ float tile[32][33];
    int mat = blockIdx.z;
    const float* s;
    float sc = 1.0f;
    if      (mat == 0)  s = w11;
    else if (mat == 1) { s = w21; sc = 0.1f; }
    else if (mat == 2)  s = w12;
    else               { s = w22; sc = 0.1f; }
    float* dst = wb + (mat + 1) * D * D;

    int tx = threadIdx.x, ty = threadIdx.y;
    int k0 = blockIdx.y * 32, n0 = blockIdx.x * 32;
    #pragma unroll
    for (int j = 0; j < 4; j++)
        tile[ty + j * 8][tx] = s[(size_t)(k0 + ty + j * 8) * D + n0 + tx];
    __syncthreads();
    #pragma unroll
    for (int j = 0; j < 4; j++)
        dst[(size_t)(n0 + ty + j * 8) * D + k0 + tx] = rndtf(tile[tx][ty + j * 8] * sc);
}

// ================= CSR build ==================================================
__global__ void deg_kernel(const int* __restrict__ dst, int* __restrict__ cnt, int E)
{
    int i = blockIdx.x * blockDim.x + threadIdx.x;
    if (i < E) atomicAdd(cnt + __ldg(dst + i), 1);
}

__global__ void scan_kernel(const int* __restrict__ cnt, int* __restrict__ off,
                            int* __restrict__ cur, float* __restrict__ norm, int n)
{
    __shared__ int sh[1024];
    const int CH = 20;
    int t = threadIdx.x;
    int base = t * CH;
    int v[CH];
    if (base + CH <= n) {
        #pragma unroll
        for (int i = 0; i < CH / 4; i++) {
            int4 q = *reinterpret_cast<const int4*>(cnt + base + i * 4);
            v[i * 4 + 0] = q.x; v[i * 4 + 1] = q.y;
            v[i * 4 + 2] = q.z; v[i * 4 + 3] = q.w;
        }
    } else {
        #pragma unroll
        for (int i = 0; i < CH; i++) v[i] = (base + i < n) ? cnt[base + i] : 0;
    }
    int s = 0;
    #pragma unroll
    for (int i = 0; i < CH; i++) s += v[i];
    sh[t] = s;
    __syncthreads();
    for (int d = 1; d < 1024; d <<= 1) {
        int x = (t >= d) ? sh[t - d] : 0;
        __syncthreads();
        sh[t] += x;
        __syncthreads();
    }
    int run = sh[t] - s;
    #pragma unroll
    for (int i = 0; i < CH; i++) {
        int idx = base + i;
        if (idx < n) {
            off[idx] = run;
            cur[idx] = run;
            norm[idx] = rsqrtf(fmaxf((float)v[i], 1.0f));
            run += v[i];
        }
    }
    if (t == 1023) off[n] = sh[1023];
}

__global__ void fill_kernel(const int* __restrict__ src, const int* __restrict__ dst,
                            int* __restrict__ cur, int* __restrict__ csr, int E)
{
    int i = blockIdx.x * blockDim.x + threadIdx.x;
    if (i < E) {
        int d = __ldg(dst + i);
        int p = atomicAdd(cur + d, 1);
        csr[p] = __ldg(src + i);
    }
}

// ================= aggregation: fp16 gather, fp32 accumulate =================
// F[n,:] = rndtf( 0.9 * norm[n] * sum norm[src]*h16[src,:] )
__global__ __launch_bounds__(128)
void agg_kernel(const __half* __restrict__ h, const float* __restrict__ norm,
                const int* __restrict__ off, const int* __restrict__ csr,
                float* __restrict__ F)
{
    int node = blockIdx.x;
    int c    = threadIdx.x * 4;
    int s0 = __ldg(off + node);
    int s1 = __ldg(off + node + 1);
    float4 acc = make_float4(0.f, 0.f, 0.f, 0.f);
    int j = s0;
    for (; j + 3 < s1; j += 4) {
        int   si[4];
        float wi[4];
        #pragma unroll
        for (int u = 0; u < 4; u++) si[u] = __ldg(csr + j + u);
        #pragma unroll
        for (int u = 0; u < 4; u++) wi[u] = __ldg(norm + si[u]);
        uint2 q[4];
        #pragma unroll
        for (int u = 0; u < 4; u++)
            q[u] = *reinterpret_cast<const uint2*>(h + (size_t)si[u] * D + c);
        #pragma unroll
        for (int u = 0; u < 4; u++) {
            float2 lo = __half22float2(*reinterpret_cast<__half2*>(&q[u].x));
            float2 hi = __half22float2(*reinterpret_cast<__half2*>(&q[u].y));
            acc.x += wi[u] * lo.x;
            acc.y += wi[u] * lo.y;
            acc.z += wi[u] * hi.x;
            acc.w += wi[u] * hi.y;
        }
    }
    for (; j < s1; j++) {
        int sA = __ldg(csr + j);
        float wA = __ldg(norm + sA);
        uint2 q = *reinterpret_cast<const uint2*>(h + (size_t)sA * D + c);
        float2 lo = __half22float2(*reinterpret_cast<__half2*>(&q.x));
        float2 hi = __half22float2(*reinterpret_cast<__half2*>(&q.y));
        acc.x += wA * lo.x; acc.y += wA * lo.y;
        acc.z += wA * hi.x; acc.w += wA * hi.y;
    }
    float wn = __ldg(norm + node) * 0.9f;
    float4 r;
    r.x = rndtf(acc.x * wn);
    r.y = rndtf(acc.y * wn);
    r.z = rndtf(acc.z * wn);
    r.w = rndtf(acc.w * wn);
    *reinterpret_cast<float4*>(F + (size_t)node * D + c) = r;
}

// ================= unified tf32 GEMM (cp.async + ldmatrix) ===================
#define STG 3
#define AE 4096

// LAYER=false: out = A0 @ B0^T + bias
// LAYER=true:  out = relu(beta*(A0@B0 + A1@B1) + (1-beta)*(A0 + 0.1*A1) + bias)
// OUT32 -> C fp32;  OUT16 -> C16 fp16 mirror
template <bool LAYER, bool OUT32, bool OUT16>
__global__ __launch_bounds__(256, 2)
void gemm_tc(const float* __restrict__ A0, const float* __restrict__ A1,
             const float* __restrict__ B0, const float* __restrict__ B1,
             const float* __restrict__ bias, float* __restrict__ C,
             __half* __restrict__ C16, int M, float beta)
{
    extern __shared__ unsigned sm[];
    const int tid = threadIdx.x, lane = tid & 31, warp = tid >> 5;
    const int wm = warp >> 2, wn = warp & 3;
    const int bm = blockIdx.y * 128, bn = blockIdx.x * 128;
    const uint32_t smb = (uint32_t)__cvta_generic_to_shared(sm);
    const uint32_t smbB = smb + STG * AE * 4u;

    float acc[4][4][4] = {};

    int lrow[4], lc[4], avalid[4];
    uint32_t dA[4], dB[4];
    #pragma unroll
    for (int i = 0; i < 4; i++) {
        int cid = tid + i * 256;
        lrow[i] = cid >> 3;
        lc[i]   = cid & 7;
        int cs  = lc[i] ^ (lrow[i] & 7);
        dA[i] = smb  + (uint32_t)(lrow[i] * 32 + cs * 4) * 4u;
        dB[i] = dA[i] + STG * AE * 4u;
        avalid[i] = (bm + lrow[i] < M) ? 16 : 0;
    }

    auto issue = [&](int stage, int t) {
        const float* Ap;
        const float* Bp;
        int k0;
        if (LAYER) {
            bool second = (t >= 16);
            Ap = second ? A1 : A0;
            Bp = second ? B1 : B0;
            k0 = (t & 15) * 32;
        } else {
            Ap = A0; Bp = B0; k0 = t * 32;
        }
        uint32_t so = (uint32_t)stage * AE * 4u;
        #pragma unroll
        for (int i = 0; i < 4; i++) {
            const float* as = Ap + (size_t)(avalid[i] ? bm + lrow[i] : 0) * D + k0 + lc[i] * 4;
            cp16(dA[i] + so, as, avalid[i]);
            const float* bs = Bp + (size_t)(bn + lrow[i]) * D + k0 + lc[i] * 4;
            cp16(dB[i] + so, bs, 16);
        }
        cp_commit();
    };

    const int hiA = (lane >> 4) & 1;
    uint32_t abase[4];
    int akey[4];
    #pragma unroll
    for (int mt = 0; mt < 4; mt++) {
        int row = wm * 64 + mt * 16 + (lane & 15);
        akey[mt]  = row & 7;
        abase[mt] = (uint32_t)row * 128u;
    }
    const int hiB = (lane >> 3) & 1;
    uint32_t bbase[2];
    int bkey[2];
    #pragma unroll
    for (int np = 0; np < 2; np++) {
        int row = wn * 32 + np * 16 + (lane & 7) + ((lane & 16) ? 8 : 0);
        bkey[np]  = row & 7;
        bbase[np] = (uint32_t)row * 128u;
    }

    auto compute = [&](int stage) {
        uint32_t sa = smb  + (uint32_t)stage * AE * 4u;
        uint32_t sb = smbB + (uint32_t)stage * AE * 4u;
        #pragma unroll
        for (int kc = 0; kc < 4; kc++) {
            unsigned af[4][4], bf[4][2];
            #pragma unroll
            for (int mt = 0; mt < 4; mt++) {
                uint32_t addr = sa + abase[mt] + (uint32_t)(((2 * kc + hiA) ^ akey[mt]) << 4);
                ldsm4(af[mt][0], af[mt][1], af[mt][2], af[mt][3], addr);
            }
            #pragma unroll
            for (int np = 0; np < 2; np++) {
                uint32_t addr = sb + bbase[np] + (uint32_t)(((2 * kc + hiB) ^ bkey[np]) << 4);
                ldsm4(bf[2 * np][0], bf[2 * np][1], bf[2 * np + 1][0], bf[2 * np + 1][1], addr);
            }
            #pragma unroll
            for (int mt = 0; mt < 4; mt++)
                #pragma unroll
                for (int nt = 0; nt < 4; nt++)
                    mma8(acc[mt][nt], af[mt][0], af[mt][1], af[mt][2], af[mt][3],
                         bf[nt][0], bf[nt][1]);
        }
    };

    const int T = LAYER ? 32 : 16;
    issue(0, 0);
    issue(1, 1);
    for (int t = 0; t < T; t++) {
        cp_wait<STG - 2>();
        __syncthreads();
        if (t + STG - 1 < T) issue((t + STG - 1) % STG, t + STG - 1);
        else                 cp_commit();
        compute(t % STG);
    }

    const int grp = lane >> 2, tig = lane & 3;
    const float ob = 1.0f - beta;
    #pragma unroll
    for (int mt = 0; mt < 4; mt++) {
        int gr[2];
        gr[0] = bm + wm * 64 + mt * 16 + grp;
        gr[1] = gr[0] + 8;
        #pragma unroll
        for (int nt = 0; nt < 4; nt++) {
            int gc = bn + wn * 32 + nt * 8 + tig * 2;
            float2 bb = *reinterpret_cast<const float2*>(bias + gc);
            #pragma unroll
            for (int hh = 0; hh < 2; hh++) {
                if (gr[hh] >= M) continue;
                size_t base = (size_t)gr[hh] * D + gc;
                float2 v;
                if (LAYER) {
                    float2 f  = *reinterpret_cast<const float2*>(A0 + base);
                    float2 h0 = *reinterpret_cast<const float2*>(A1 + base);
                    v.x = fmaxf(beta * acc[mt][nt][2 * hh + 0] + ob * (f.x + 0.1f * h0.x) + bb.x, 0.f);
                    v.y = fmaxf(beta * acc[mt][nt][2 * hh + 1] + ob * (f.y + 0.1f * h0.y) + bb.y, 0.f);
                } else {
                    v.x = acc[mt][nt][2 * hh + 0] + bb.x;
                    v.y = acc[mt][nt][2 * hh + 1] + bb.y;
                }
                if (OUT32)
                    *reinterpret_cast<float2*>(C + base) = v;
                if (OUT16)
                    *reinterpret_cast<__half2*>(C16 + base) = __floats2half2_rn(v.x, v.y);
            }
        }
    }
}

// ================= host orchestration =========================================
extern "C" void kernel_launch(void* const* d_in, const int* in_sizes, int n_in,
                              void* d_out, int out_size)
{
    const float* feat = (const float*)d_in[0];
    const int*   src  = (const int*)  d_in[1];
    const int*   dst  = (const int*)  d_in[2];
    const float* fc_w = (const float*)d_in[3];
    const float* fc_b = (const float*)d_in[4];
    const float* w1_1 = (const float*)d_in[5];
    const float* w2_1 = (const float*)d_in[6];
    const float* b_1  = (const float*)d_in[7];
    const float* w1_2 = (const float*)d_in[8];
    const float* w2_2 = (const float*)d_in[9];
    const float* b_2  = (const float*)d_in[10];
    float* out = (float*)d_out;

    int M = in_sizes[0] / D;
    int E = in_sizes[1];

    float *H, *F, *WB, *NORM;
    __half *H16, *R16;
    int *CNT, *OFF, *CUR, *CSR;
    cudaGetSymbolAddress((void**)&H,    g_H);
    cudaGetSymbolAddress((void**)&F,    g_F);
    cudaGetSymbolAddress((void**)&H16,  g_H16);
    cudaGetSymbolAddress((void**)&R16,  g_R16);
    cudaGetSymbolAddress((void**)&WB,   g_WB);
    cudaGetSymbolAddress((void**)&NORM, g_norm);
    cudaGetSymbolAddress((void**)&CNT,  g_cnt);
    cudaGetSymbolAddress((void**)&OFF,  g_off);
    cudaGetSymbolAddress((void**)&CUR,  g_cur);
    cudaGetSymbolAddress((void**)&CSR,  g_csr);

    const int smem = STG * AE * 2 * 4;   // 98304
    cudaFuncSetAttribute((const void*)gemm_tc<false, true,  true >, cudaFuncAttributeMaxDynamicSharedMemorySize, smem);
    cudaFuncSetAttribute((const void*)gemm_tc<true,  false, true >, cudaFuncAttributeMaxDynamicSharedMemorySize, smem);
    cudaFuncSetAttribute((const void*)gemm_tc<true,  true,  false>, cudaFuncAttributeMaxDynamicSharedMemorySize, smem);

    dim3 grid(D / 128, (M + 127) / 128);

    cudaMemsetAsync(CNT, 0, (size_t)M * sizeof(int));
    deg_kernel<<<(E + 255) / 256, 256>>>(dst, CNT, E);
    prep_fc<<<(D * D + 255) / 256, 256>>>(fc_w, WB);
    prep_wT<<<dim3(16, 16, 4), dim3(32, 8)>>>(w1_1, w2_1, w1_2, w2_2, WB);
    scan_kernel<<<1, 1024>>>(CNT, OFF, CUR, NORM, M);

    gemm_tc<false, true, true><<<grid, 256, smem>>>(feat, nullptr, WB, nullptr,
                                                    fc_b, H, H16, M, 0.f);

    fill_kernel<<<(E + 255) / 256, 256>>>(src, dst, CUR, CSR, E);

    const float beta1 = logf(2.0f);
    const float beta2 = logf(1.5f);

    agg_kernel<<<M, 128>>>(H16, NORM, OFF, CSR, F);
    gemm_tc<true, false, true><<<grid, 256, smem>>>(F, H, WB + 1 * D * D, WB + 2 * D * D,
                                                    b_1, nullptr, R16, M, beta1);

    agg_kernel<<<M, 128>>>(R16, NORM, OFF, CSR, F);
    gemm_tc<true, true, false><<<grid, 256, smem>>>(F, H, WB + 3 * D * D, WB + 4 * D * D,
                                                    b_2, out, nullptr, M, beta2);
}

// round 12
// speedup vs baseline: 1.2988x; 1.2988x over previous
#include <cuda_runtime.h>
#include <cuda_fp16.h>
#include <cstdint>
#include <math.h>

#define NMAX 20000
#define EMAX 320000
#define D 512

// ---------------- scratch (static device globals; no allocation) -------------
__device__ __half g_H16[NMAX * D];
__device__ __half g_R16[NMAX * D];
__device__ __half g_F16[NMAX * D];
__device__ float  g_WB [D * D];         // tf32-rounded fc weights [N][K]
__device__ __half g_W16[4 * D * D];     // fp16 layer weights [N][K], 0.1 baked into W2
__device__ float  g_norm[NMAX];
__device__ int    g_cnt [NMAX];
__device__ int    g_off [NMAX + 1];
__device__ int    g_cur [NMAX + 1];
__device__ int    g_csr [EMAX];

// ================= small helpers ==============================================
__device__ __forceinline__ unsigned f2tf(float x)
{
    unsigned r;
    asm("cvt.rna.tf32.f32 %0, %1;" : "=r"(r) : "f"(x));
    return r;
}
__device__ __forceinline__ float rndtf(float x) { return __uint_as_float(f2tf(x)); }

__device__ __forceinline__ void cp16(uint32_t dst, const void* src, int bytes)
{
    asm volatile("cp.async.cg.shared.global [%0], [%1], 16, %2;"
                 :: "r"(dst), "l"(src), "r"(bytes));
}
__device__ __forceinline__ void cp_commit() { asm volatile("cp.async.commit_group;"); }
template <int N> __device__ __forceinline__ void cp_wait()
{ asm volatile("cp.async.wait_group %0;" :: "n"(N)); }

__device__ __forceinline__ void mma8(float* c,
                                     unsigned a0, unsigned a1, unsigned a2, unsigned a3,
                                     unsigned b0, unsigned b1)
{
    asm volatile(
        "mma.sync.aligned.m16n8k8.row.col.f32.tf32.tf32.f32 "
        "{%0,%1,%2,%3},{%4,%5,%6,%7},{%8,%9},{%0,%1,%2,%3};"
        : "+f"(c[0]), "+f"(c[1]), "+f"(c[2]), "+f"(c[3])
        : "r"(a0), "r"(a1), "r"(a2), "r"(a3), "r"(b0), "r"(b1));
}

__device__ __forceinline__ void mma16(float* c,
                                      unsigned a0, unsigned a1, unsigned a2, unsigned a3,
                                      unsigned b0, unsigned b1)
{
    asm volatile(
        "mma.sync.aligned.m16n8k16.row.col.f32.f16.f16.f32 "
        "{%0,%1,%2,%3},{%4,%5,%6,%7},{%8,%9},{%0,%1,%2,%3};"
        : "+f"(c[0]), "+f"(c[1]), "+f"(c[2]), "+f"(c[3])
        : "r"(a0), "r"(a1), "r"(a2), "r"(a3), "r"(b0), "r"(b1));
}

__device__ __forceinline__ void ldsm4(unsigned& r0, unsigned& r1, unsigned& r2, unsigned& r3,
                                      uint32_t addr)
{
    asm volatile("ldmatrix.sync.aligned.m8n8.x4.shared.b16 {%0,%1,%2,%3}, [%4];"
                 : "=r"(r0), "=r"(r1), "=r"(r2), "=r"(r3) : "r"(addr));
}

// ================= weight prep ===============================================
__global__ void prep_fc(const float* __restrict__ fcw, float* __restrict__ wb)
{
    int i = blockIdx.x * blockDim.x + threadIdx.x;
    if (i < D * D) wb[i] = rndtf(fcw[i]);
}

// layer weights [K][N] -> [N][K] fp16, 0.1 baked into W2
__global__ void prep_wT16(const float* __restrict__ w11, const float* __restrict__ w21,
                          const float* __restrict__ w12, const float* __restrict__ w22,
                          __half* __restrict__ wb)
{
    __shared__ float tile[32][33];
    int mat = blockIdx.z;
    const float* s;
    float sc = 1.0f;
    if      (mat == 0)  s = w11;
    else if (mat == 1) { s = w21; sc = 0.1f; }
    else if (mat == 2)  s = w12;
    else               { s = w22; sc = 0.1f; }
    __half* dst = wb + (size_t)mat * D * D;

    int tx = threadIdx.x, ty = threadIdx.y;
    int k0 = blockIdx.y * 32, n0 = blockIdx.x * 32;
    #pragma unroll
    for (int j = 0; j < 4; j++)
        tile[ty + j * 8][tx] = s[(size_t)(k0 + ty + j * 8) * D + n0 + tx];
    __syncthreads();
    #pragma unroll
    for (int j = 0; j < 4; j++)
        dst[(size_t)(n0 + ty + j * 8) * D + k0 + tx] = __float2half(tile[tx][ty + j * 8] * sc);
}

// ================= CSR build ==================================================
__global__ void deg_kernel(const int* __restrict__ dst, int* __restrict__ cnt, int E)
{
    int i = blockIdx.x * blockDim.x + threadIdx.x;
    if (i < E) atomicAdd(cnt + __ldg(dst + i), 1);
}

__global__ void scan_kernel(const int* __restrict__ cnt, int* __restrict__ off,
                            int* __restrict__ cur, float* __restrict__ norm, int n)
{
    __shared__ int sh[1024];
    const int CH = 20;
    int t = threadIdx.x;
    int base = t * CH;
    int v[CH];
    if (base + CH <= n) {
        #pragma unroll
        for (int i = 0; i < CH / 4; i++) {
            int4 q = *reinterpret_cast<const int4*>(cnt + base + i * 4);
            v[i * 4 + 0] = q.x; v[i * 4 + 1] = q.y;
            v[i * 4 + 2] = q.z; v[i * 4 + 3] = q.w;
        }
    } else {
        #pragma unroll
        for (int i = 0; i < CH; i++) v[i] = (base + i < n) ? cnt[base + i] : 0;
    }
    int s = 0;
    #pragma unroll
    for (int i = 0; i < CH; i++) s += v[i];
    sh[t] = s;
    __syncthreads();
    for (int d = 1; d < 1024; d <<= 1) {
        int x = (t >= d) ? sh[t - d] : 0;
        __syncthreads();
        sh[t] += x;
        __syncthreads();
    }
    int run = sh[t] - s;
    int offv[CH];
    float nv[CH];
    #pragma unroll
    for (int i = 0; i < CH; i++) {
        offv[i] = run;
        nv[i]   = rsqrtf(fmaxf((float)v[i], 1.0f));
        run += v[i];
    }
    if (base + CH <= n) {
        #pragma unroll
        for (int i = 0; i < CH; i += 4) {
            int4 o = make_int4(offv[i], offv[i + 1], offv[i + 2], offv[i + 3]);
            *reinterpret_cast<int4*>(off + base + i) = o;
            *reinterpret_cast<int4*>(cur + base + i) = o;
            *reinterpret_cast<float4*>(norm + base + i) =
                make_float4(nv[i], nv[i + 1], nv[i + 2], nv[i + 3]);
        }
    } else {
        for (int i = 0; i < CH; i++) {
            int idx = base + i;
            if (idx < n) { off[idx] = offv[i]; cur[idx] = offv[i]; norm[idx] = nv[i]; }
        }
    }
    if (t == 1023) off[n] = sh[1023];
}

__global__ void fill_kernel(const int* __restrict__ src, const int* __restrict__ dst,
                            int* __restrict__ cur, int* __restrict__ csr, int E)
{
    int i = blockIdx.x * blockDim.x + threadIdx.x;
    if (i < E) {
        int d = __ldg(dst + i);
        int p = atomicAdd(cur + d, 1);
        csr[p] = __ldg(src + i);
    }
}

// ================= aggregation: fp16 gather -> fp16 out ======================
// F16[n,:] = half( 0.9 * norm[n] * sum norm[src]*h16[src,:] )
__global__ __launch_bounds__(128)
void agg_kernel(const __half* __restrict__ h, const float* __restrict__ norm,
                const int* __restrict__ off, const int* __restrict__ csr,
                __half* __restrict__ F)
{
    int node = blockIdx.x;
    int c    = threadIdx.x * 4;
    int s0 = __ldg(off + node);
    int s1 = __ldg(off + node + 1);
    float4 acc = make_float4(0.f, 0.f, 0.f, 0.f);
    int j = s0;
    for (; j + 3 < s1; j += 4) {
        int   si[4];
        float wi[4];
        #pragma unroll
        for (int u = 0; u < 4; u++) si[u] = __ldg(csr + j + u);
        #pragma unroll
        for (int u = 0; u < 4; u++) wi[u] = __ldg(norm + si[u]);
        uint2 q[4];
        #pragma unroll
        for (int u = 0; u < 4; u++)
            q[u] = *reinterpret_cast<const uint2*>(h + (size_t)si[u] * D + c);
        #pragma unroll
        for (int u = 0; u < 4; u++) {
            float2 lo = __half22float2(*reinterpret_cast<__half2*>(&q[u].x));
            float2 hi = __half22float2(*reinterpret_cast<__half2*>(&q[u].y));
            acc.x += wi[u] * lo.x;
            acc.y += wi[u] * lo.y;
            acc.z += wi[u] * hi.x;
            acc.w += wi[u] * hi.y;
        }
    }
    for (; j < s1; j++) {
        int sA = __ldg(csr + j);
        float wA = __ldg(norm + sA);
        uint2 q = *reinterpret_cast<const uint2*>(h + (size_t)sA * D + c);
        float2 lo = __half22float2(*reinterpret_cast<__half2*>(&q.x));
        float2 hi = __half22float2(*reinterpret_cast<__half2*>(&q.y));
        acc.x += wA * lo.x; acc.y += wA * lo.y;
        acc.z += wA * hi.x; acc.w += wA * hi.y;
    }
    float wn = __ldg(norm + node) * 0.9f;
    __half2 lo = __floats2half2_rn(acc.x * wn, acc.y * wn);
    __half2 hi = __floats2half2_rn(acc.z * wn, acc.w * wn);
    uint2 o;
    o.x = *reinterpret_cast<uint32_t*>(&lo);
    o.y = *reinterpret_cast<uint32_t*>(&hi);
    *reinterpret_cast<uint2*>(F + (size_t)node * D + c) = o;
}

// ================= gemm_fc: tf32, A fp32 feat, out fp16 H16 ==================
#define STG 3
#define AE 4096

__global__ __launch_bounds__(256, 2)
void gemm_fc_tc(const float* __restrict__ A, const float* __restrict__ Bw,
                const float* __restrict__ bias, __half* __restrict__ C16, int M)
{
    extern __shared__ unsigned sm[];
    const int tid = threadIdx.x, lane = tid & 31, warp = tid >> 5;
    const int wm = warp >> 2, wn = warp & 3;
    const int bm = blockIdx.y * 128, bn = blockIdx.x * 128;
    const uint32_t smb = (uint32_t)__cvta_generic_to_shared(sm);
    const uint32_t smbB = smb + STG * AE * 4u;

    float acc[4][4][4] = {};

    int lrow[4], lc[4], avalid[4];
    uint32_t dA[4], dB[4];
    #pragma unroll
    for (int i = 0; i < 4; i++) {
        int cid = tid + i * 256;
        lrow[i] = cid >> 3;
        lc[i]   = cid & 7;
        int cs  = lc[i] ^ (lrow[i] & 7);
        dA[i] = smb  + (uint32_t)(lrow[i] * 32 + cs * 4) * 4u;
        dB[i] = dA[i] + STG * AE * 4u;
        avalid[i] = (bm + lrow[i] < M) ? 16 : 0;
    }

    auto issue = [&](int stage, int t) {
        int k0 = t * 32;
        uint32_t so = (uint32_t)stage * AE * 4u;
        #pragma unroll
        for (int i = 0; i < 4; i++) {
            const float* as = A + (size_t)(avalid[i] ? bm + lrow[i] : 0) * D + k0 + lc[i] * 4;
            cp16(dA[i] + so, as, avalid[i]);
            const float* bs = Bw + (size_t)(bn + lrow[i]) * D + k0 + lc[i] * 4;
            cp16(dB[i] + so, bs, 16);
        }
        cp_commit();
    };

    const int hiA = (lane >> 4) & 1;
    uint32_t abase[4];
    int akey[4];
    #pragma unroll
    for (int mt = 0; mt < 4; mt++) {
        int row = wm * 64 + mt * 16 + (lane & 15);
        akey[mt]  = row & 7;
        abase[mt] = (uint32_t)row * 128u;
    }
    const int hiB = (lane >> 3) & 1;
    uint32_t bbase[2];
    int bkey[2];
    #pragma unroll
    for (int np = 0; np < 2; np++) {
        int row = wn * 32 + np * 16 + (lane & 7) + ((lane & 16) ? 8 : 0);
        bkey[np]  = row & 7;
        bbase[np] = (uint32_t)row * 128u;
    }

    auto compute = [&](int stage) {
        uint32_t sa = smb  + (uint32_t)stage * AE * 4u;
        uint32_t sb = smbB + (uint32_t)stage * AE * 4u;
        #pragma unroll
        for (int kc = 0; kc < 4; kc++) {
            unsigned af[4][4], bf[4][2];
            #pragma unroll
            for (int mt = 0; mt < 4; mt++) {
                uint32_t addr = sa + abase[mt] + (uint32_t)(((2 * kc + hiA) ^ akey[mt]) << 4);
                ldsm4(af[mt][0], af[mt][1], af[mt][2], af[mt][3], addr);
            }
            #pragma unroll
            for (int np = 0; np < 2; np++) {
                uint32_t addr = sb + bbase[np] + (uint32_t)(((2 * kc + hiB) ^ bkey[np]) << 4);
                ldsm4(bf[2 * np][0], bf[2 * np][1], bf[2 * np + 1][0], bf[2 * np + 1][1], addr);
            }
            #pragma unroll
            for (int mt = 0; mt < 4; mt++)
                #pragma unroll
                for (int nt = 0; nt < 4; nt++)
                    mma8(acc[mt][nt], af[mt][0], af[mt][1], af[mt][2], af[mt][3],
                         bf[nt][0], bf[nt][1]);
        }
    };

    const int T = 16;
    issue(0, 0);
    issue(1, 1);
    for (int t = 0; t < T; t++) {
        cp_wait<STG - 2>();
        __syncthreads();
        if (t + STG - 1 < T) issue((t + STG - 1) % STG, t + STG - 1);
        else                 cp_commit();
        compute(t % STG);
    }

    const int grp = lane >> 2, tig = lane & 3;
    #pragma unroll
    for (int mt = 0; mt < 4; mt++) {
        int gr[2];
        gr[0] = bm + wm * 64 + mt * 16 + grp;
        gr[1] = gr[0] + 8;
        #pragma unroll
        for (int nt = 0; nt < 4; nt++) {
            int gc = bn + wn * 32 + nt * 8 + tig * 2;
            float2 bb = *reinterpret_cast<const float2*>(bias + gc);
            #pragma unroll
            for (int hh = 0; hh < 2; hh++) {
                if (gr[hh] >= M) continue;
                __half2 v = __floats2half2_rn(acc[mt][nt][2 * hh + 0] + bb.x,
                                              acc[mt][nt][2 * hh + 1] + bb.y);
                *reinterpret_cast<__half2*>(C16 + (size_t)gr[hh] * D + gc) = v;
            }
        }
    }
}

// ================= gemm_layer16: fp16 MMA m16n8k16 ===========================
// out = relu(beta*(F16@W1 + H16@W2[0.1 baked]) + (1-beta)*(F16 + 0.1*H16) + bias)
// SMEM tiles: 128 rows x 32 halves, row stride 80 B (4 x 16B chunks + 16B pad).
#define TB16 10240

template <bool OUT32>
__global__ __launch_bounds__(256, 2)
void gemm_layer16(const __half* __restrict__ A0, const __half* __restrict__ A1,
                  const __half* __restrict__ B0, const __half* __restrict__ B1,
                  const float* __restrict__ bias, float* __restrict__ C,
                  __half* __restrict__ C16, int M, float beta)
{
    extern __shared__ unsigned sm[];
    const int tid = threadIdx.x, lane = tid & 31, warp = tid >> 5;
    const int wm = warp >> 2, wn = warp & 3;
    const int bm = blockIdx.y * 128, bn = blockIdx.x * 128;
    const uint32_t smb  = (uint32_t)__cvta_generic_to_shared(sm);
    const uint32_t smbB = smb + STG * TB16;

    float acc[4][4][4] = {};

    // loaders: 512 chunks per tile each for A and B; 2 of each per thread
    int lrow[2], lch[2], avalid[2];
    uint32_t dA[2], dB[2];
    #pragma unroll
    for (int i = 0; i < 2; i++) {
        int cid = tid + i * 256;
        lrow[i] = cid >> 2;
        lch[i]  = cid & 3;
        dA[i] = smb  + (uint32_t)(lrow[i] * 80 + lch[i] * 16);
        dB[i] = smbB + (uint32_t)(lrow[i] * 80 + lch[i] * 16);
        avalid[i] = (bm + lrow[i] < M) ? 16 : 0;
    }

    auto issue = [&](int stage, int t) {
        bool second = (t >= 16);
        const __half* Ap = second ? A1 : A0;
        const __half* Bp = second ? B1 : B0;
        int k0 = (t & 15) * 32;
        uint32_t so = (uint32_t)stage * TB16;
        #pragma unroll
        for (int i = 0; i < 2; i++) {
            const __half* as = Ap + (size_t)(avalid[i] ? bm + lrow[i] : 0) * D + k0 + lch[i] * 8;
            cp16(dA[i] + so, as, avalid[i]);
            const __half* bs = Bp + (size_t)(bn + lrow[i]) * D + k0 + lch[i] * 8;
            cp16(dB[i] + so, bs, 16);
        }
        cp_commit();
    };

    // ldmatrix offsets
    uint32_t aoff[4];
    #pragma unroll
    for (int mt = 0; mt < 4; mt++) {
        int row = wm * 64 + mt * 16 + (lane & 15);
        aoff[mt] = (uint32_t)(row * 80 + ((lane >> 4) & 1) * 16);
    }
    uint32_t boff[2];
    #pragma unroll
    for (int np = 0; np < 2; np++) {
        int row = wn * 32 + np * 16 + (lane & 7) + ((lane & 16) ? 8 : 0);
        boff[np] = (uint32_t)(row * 80 + ((lane >> 3) & 1) * 16);
    }

    auto compute = [&](int stage) {
        uint32_t sa = smb  + (uint32_t)stage * TB16;
        uint32_t sb = smbB + (uint32_t)stage * TB16;
        #pragma unroll
        for (int kc = 0; kc < 2; kc++) {
            unsigned af[4][4], bf[4][2];
            #pragma unroll
            for (int mt = 0; mt < 4; mt++)
                ldsm4(af[mt][0], af[mt][1], af[mt][2], af[mt][3],
                      sa + aoff[mt] + kc * 32);
            #pragma unroll
            for (int np = 0; np < 2; np++)
                ldsm4(bf[2 * np][0], bf[2 * np][1], bf[2 * np + 1][0], bf[2 * np + 1][1],
                      sb + boff[np] + kc * 32);
            #pragma unroll
            for (int mt = 0; mt < 4; mt++)
                #pragma unroll
                for (int nt = 0; nt < 4; nt++)
                    mma16(acc[mt][nt], af[mt][0], af[mt][1], af[mt][2], af[mt][3],
                          bf[nt][0], bf[nt][1]);
        }
    };

    const int T = 32;
    issue(0, 0);
    issue(1, 1);
    for (int t = 0; t < T; t++) {
        cp_wait<STG - 2>();
        __syncthreads();
        if (t + STG - 1 < T) issue((t + STG - 1) % STG, t + STG - 1);
        else                 cp_commit();
        compute(t % STG);
    }

    const int grp = lane >> 2, tig = lane & 3;
    const float ob = 1.0f - beta;
    #pragma unroll
    for (int mt = 0; mt < 4; mt++) {
        int gr[2];
        gr[0] = bm + wm * 64 + mt * 16 + grp;
        gr[1] = gr[0] + 8;
        #pragma unroll
        for (int nt = 0; nt < 4; nt++) {
            int gc = bn + wn * 32 + nt * 8 + tig * 2;
            float2 bb = *reinterpret_cast<const float2*>(bias + gc);
            #pragma unroll
            for (int hh = 0; hh < 2; hh++) {
                if (gr[hh] >= M) continue;
                size_t base = (size_t)gr[hh] * D + gc;
                float2 f  = __half22float2(*reinterpret_cast<const __half2*>(A0 + base));
                float2 h0 = __half22float2(*reinterpret_cast<const __half2*>(A1 + base));
                float2 v;
                v.x = fmaxf(beta * acc[mt][nt][2 * hh + 0] + ob * (f.x + 0.1f * h0.x) + bb.x, 0.f);
                v.y = fmaxf(beta * acc[mt][nt][2 * hh + 1] + ob * (f.y + 0.1f * h0.y) + bb.y, 0.f);
                if (OUT32)
                    *reinterpret_cast<float2*>(C + base) = v;
                else
                    *reinterpret_cast<__half2*>(C16 + base) = __floats2half2_rn(v.x, v.y);
            }
        }
    }
}

// ================= host orchestration =========================================
extern "C" void kernel_launch(void* const* d_in, const int* in_sizes, int n_in,
                              void* d_out, int out_size)
{
    const float* feat = (const float*)d_in[0];
    const int*   src  = (const int*)  d_in[1];
    const int*   dst  = (const int*)  d_in[2];
    const float* fc_w = (const float*)d_in[3];
    const float* fc_b = (const float*)d_in[4];
    const float* w1_1 = (const float*)d_in[5];
    const float* w2_1 = (const float*)d_in[6];
    const float* b_1  = (const float*)d_in[7];
    const float* w1_2 = (const float*)d_in[8];
    const float* w2_2 = (const float*)d_in[9];
    const float* b_2  = (const float*)d_in[10];
    float* out = (float*)d_out;

    int M = in_sizes[0] / D;
    int E = in_sizes[1];

    float *WB, *NORM;
    __half *H16, *R16, *F16, *W16;
    int *CNT, *OFF, *CUR, *CSR;
    cudaGetSymbolAddress((void**)&H16,  g_H16);
    cudaGetSymbolAddress((void**)&R16,  g_R16);
    cudaGetSymbolAddress((void**)&F16,  g_F16);
    cudaGetSymbolAddress((void**)&WB,   g_WB);
    cudaGetSymbolAddress((void**)&W16,  g_W16);
    cudaGetSymbolAddress((void**)&NORM, g_norm);
    cudaGetSymbolAddress((void**)&CNT,  g_cnt);
    cudaGetSymbolAddress((void**)&OFF,  g_off);
    cudaGetSymbolAddress((void**)&CUR,  g_cur);
    cudaGetSymbolAddress((void**)&CSR,  g_csr);

    const int smem_fc = STG * AE * 2 * 4;     // 98304
    const int smem_l  = STG * TB16 * 2;       // 61440
    cudaFuncSetAttribute(gemm_fc_tc, cudaFuncAttributeMaxDynamicSharedMemorySize, smem_fc);
    cudaFuncSetAttribute((const void*)gemm_layer16<false>, cudaFuncAttributeMaxDynamicSharedMemorySize, smem_l);
    cudaFuncSetAttribute((const void*)gemm_layer16<true >, cudaFuncAttributeMaxDynamicSharedMemorySize, smem_l);

    dim3 grid(D / 128, (M + 127) / 128);

    cudaMemsetAsync(CNT, 0, (size_t)M * sizeof(int));
    deg_kernel<<<(E + 255) / 256, 256>>>(dst, CNT, E);
    prep_fc<<<(D * D + 255) / 256, 256>>>(fc_w, WB);
    prep_wT16<<<dim3(16, 16, 4), dim3(32, 8)>>>(w1_1, w2_1, w1_2, w2_2, W16);
    scan_kernel<<<1, 1024>>>(CNT, OFF, CUR, NORM, M);

    gemm_fc_tc<<<grid, 256, smem_fc>>>(feat, WB, fc_b, H16, M);

    fill_kernel<<<(E + 255) / 256, 256>>>(src, dst, CUR, CSR, E);

    const float beta1 = logf(2.0f);
    const float beta2 = logf(1.5f);

    agg_kernel<<<M, 128>>>(H16, NORM, OFF, CSR, F16);
    gemm_layer16<false><<<grid, 256, smem_l>>>(F16, H16, W16 + 0 * D * D, W16 + 1 * D * D,
                                               b_1, nullptr, R16, M, beta1);

    agg_kernel<<<M, 128>>>(R16, NORM, OFF, CSR, F16);
    gemm_layer16<true><<<grid, 256, smem_l>>>(F16, H16, W16 + 2 * D * D, W16 + 3 * D * D,
                                              b_2, out, nullptr, M, beta2);
}

// round 13
// speedup vs baseline: 1.3709x; 1.0555x over previous
#include <cuda_runtime.h>
#include <cuda_fp16.h>
#include <cstdint>
#include <math.h>

#define NMAX 20000
#define EMAX 320000
#define D 512

// ---------------- scratch (static device globals; no allocation) -------------
__device__ __half g_H16 [NMAX * D];
__device__ __half g_R16 [NMAX * D];
__device__ __half g_F16 [NMAX * D];
__device__ __half g_FT16[NMAX * D];      // feat in fp16
__device__ __half g_W16 [5 * D * D];     // fp16 weights [N][K]: fc, w1_1, w2_1(x0.1), w1_2, w2_2(x0.1)
__device__ float  g_norm[NMAX];
__device__ int    g_cnt [NMAX];          // zero-init; scan re-zeroes each call
__device__ int    g_off [NMAX + 1];
__device__ int    g_cur [NMAX + 1];
__device__ int    g_csr [EMAX];

// ================= small helpers ==============================================
__device__ __forceinline__ void cp16(uint32_t dst, const void* src, int bytes)
{
    asm volatile("cp.async.cg.shared.global [%0], [%1], 16, %2;"
                 :: "r"(dst), "l"(src), "r"(bytes));
}
__device__ __forceinline__ void cp_commit() { asm volatile("cp.async.commit_group;"); }
template <int N> __device__ __forceinline__ void cp_wait()
{ asm volatile("cp.async.wait_group %0;" :: "n"(N)); }

__device__ __forceinline__ void mma16(float* c,
                                      unsigned a0, unsigned a1, unsigned a2, unsigned a3,
                                      unsigned b0, unsigned b1)
{
    asm volatile(
        "mma.sync.aligned.m16n8k16.row.col.f32.f16.f16.f32 "
        "{%0,%1,%2,%3},{%4,%5,%6,%7},{%8,%9},{%0,%1,%2,%3};"
        : "+f"(c[0]), "+f"(c[1]), "+f"(c[2]), "+f"(c[3])
        : "r"(a0), "r"(a1), "r"(a2), "r"(a3), "r"(b0), "r"(b1));
}

__device__ __forceinline__ void ldsm4(unsigned& r0, unsigned& r1, unsigned& r2, unsigned& r3,
                                      uint32_t addr)
{
    asm volatile("ldmatrix.sync.aligned.m8n8.x4.shared.b16 {%0,%1,%2,%3}, [%4];"
                 : "=r"(r0), "=r"(r1), "=r"(r2), "=r"(r3) : "r"(addr));
}

// ================= fused prep: deg + feat16 + fcw16 + layer-weight transpose ==
// block ranges: [0,nbd) deg | [nbd,nbd+nbf) feat16 | +128 fcw16 | +1024 wT16
__global__ __launch_bounds__(256)
void prep_all(const int* __restrict__ dst, int* __restrict__ cnt, int E, int nbd,
              const float* __restrict__ feat, __half* __restrict__ f16, int featN, int nbf,
              const float* __restrict__ fcw,
              const float* __restrict__ w11, const float* __restrict__ w21,
              const float* __restrict__ w12, const float* __restrict__ w22,
              __half* __restrict__ w16)
{
    __shared__ float tile[32][33];
    const int b = blockIdx.x, tid = threadIdx.x;

    if (b < nbd) {                                   // degree histogram
        int i = b * 256 + tid;
        if (i < E) atomicAdd(cnt + __ldg(dst + i), 1);
        return;
    }
    if (b < nbd + nbf) {                             // feat -> fp16
        int i = (b - nbd) * 2048 + tid * 8;
        if (i + 8 <= featN) {
            float4 a = *reinterpret_cast<const float4*>(feat + i);
            float4 c = *reinterpret_cast<const float4*>(feat + i + 4);
            __half2 h0 = __floats2half2_rn(a.x, a.y);
            __half2 h1 = __floats2half2_rn(a.z, a.w);
            __half2 h2 = __floats2half2_rn(c.x, c.y);
            __half2 h3 = __floats2half2_rn(c.z, c.w);
            uint4 o;
            o.x = *reinterpret_cast<uint32_t*>(&h0);
            o.y = *reinterpret_cast<uint32_t*>(&h1);
            o.z = *reinterpret_cast<uint32_t*>(&h2);
            o.w = *reinterpret_cast<uint32_t*>(&h3);
            *reinterpret_cast<uint4*>(f16 + i) = o;
        }
        return;
    }
    if (b < nbd + nbf + 128) {                       // fc_w -> fp16 (already [N][K])
        int i = (b - nbd - nbf) * 2048 + tid * 8;
        float4 a = *reinterpret_cast<const float4*>(fcw + i);
        float4 c = *reinterpret_cast<const float4*>(fcw + i + 4);
        __half2 h0 = __floats2half2_rn(a.x, a.y);
        __half2 h1 = __floats2half2_rn(a.z, a.w);
        __half2 h2 = __floats2half2_rn(c.x, c.y);
        __half2 h3 = __floats2half2_rn(c.z, c.w);
        uint4 o;
        o.x = *reinterpret_cast<uint32_t*>(&h0);
        o.y = *reinterpret_cast<uint32_t*>(&h1);
        o.z = *reinterpret_cast<uint32_t*>(&h2);
        o.w = *reinterpret_cast<uint32_t*>(&h3);
        *reinterpret_cast<uint4*>(w16 + i) = o;
        return;
    }
    // layer weights [K][N] -> [N][K] fp16, 0.1 baked into W2
    int b2  = b - nbd - nbf - 128;
    int mat = b2 >> 8;
    int rem = b2 & 255;
    int n0 = (rem & 15) * 32, k0 = (rem >> 4) * 32;
    int tx = tid & 31, ty = tid >> 5;
    const float* s;
    float sc = 1.0f;
    if      (mat == 0)  s = w11;
    else if (mat == 1) { s = w21; sc = 0.1f; }
    else if (mat == 2)  s = w12;
    else               { s = w22; sc = 0.1f; }
    __half* dstw = w16 + (size_t)(mat + 1) * D * D;
    #pragma unroll
    for (int j = 0; j < 4; j++)
        tile[ty + j * 8][tx] = s[(size_t)(k0 + ty + j * 8) * D + n0 + tx];
    __syncthreads();
    #pragma unroll
    for (int j = 0; j < 4; j++)
        dstw[(size_t)(n0 + ty + j * 8) * D + k0 + tx] = __float2half(tile[tx][ty + j * 8] * sc);
}

// ================= scan: prefix + cur + norm + cnt re-zero ====================
__global__ void scan_kernel(int* __restrict__ cnt, int* __restrict__ off,
                            int* __restrict__ cur, float* __restrict__ norm, int n)
{
    __shared__ int sh[1024];
    const int CH = 20;
    int t = threadIdx.x;
    int base = t * CH;
    int v[CH];
    if (base + CH <= n) {
        #pragma unroll
        for (int i = 0; i < CH / 4; i++) {
            int4 q = *reinterpret_cast<const int4*>(cnt + base + i * 4);
            v[i * 4 + 0] = q.x; v[i * 4 + 1] = q.y;
            v[i * 4 + 2] = q.z; v[i * 4 + 3] = q.w;
        }
    } else {
        #pragma unroll
        for (int i = 0; i < CH; i++) v[i] = (base + i < n) ? cnt[base + i] : 0;
    }
    int s = 0;
    #pragma unroll
    for (int i = 0; i < CH; i++) s += v[i];
    sh[t] = s;
    __syncthreads();
    for (int d = 1; d < 1024; d <<= 1) {
        int x = (t >= d) ? sh[t - d] : 0;
        __syncthreads();
        sh[t] += x;
        __syncthreads();
    }
    int run = sh[t] - s;
    int offv[CH];
    float nv[CH];
    #pragma unroll
    for (int i = 0; i < CH; i++) {
        offv[i] = run;
        nv[i]   = rsqrtf(fmaxf((float)v[i], 1.0f));
        run += v[i];
    }
    if (base + CH <= n) {
        #pragma unroll
        for (int i = 0; i < CH; i += 4) {
            int4 o = make_int4(offv[i], offv[i + 1], offv[i + 2], offv[i + 3]);
            *reinterpret_cast<int4*>(off + base + i) = o;
            *reinterpret_cast<int4*>(cur + base + i) = o;
            *reinterpret_cast<float4*>(norm + base + i) =
                make_float4(nv[i], nv[i + 1], nv[i + 2], nv[i + 3]);
            *reinterpret_cast<int4*>(cnt + base + i) = make_int4(0, 0, 0, 0);
        }
    } else {
        for (int i = 0; i < CH; i++) {
            int idx = base + i;
            if (idx < n) {
                off[idx] = offv[i]; cur[idx] = offv[i]; norm[idx] = nv[i];
                cnt[idx] = 0;
            }
        }
    }
    if (t == 1023) off[n] = sh[1023];
}

__global__ void fill_kernel(const int* __restrict__ src, const int* __restrict__ dst,
                            int* __restrict__ cur, int* __restrict__ csr, int E)
{
    int i = blockIdx.x * blockDim.x + threadIdx.x;
    if (i < E) {
        int d = __ldg(dst + i);
        int p = atomicAdd(cur + d, 1);
        csr[p] = __ldg(src + i);
    }
}

// ================= aggregation: fp16 gather -> fp16 out ======================
__global__ __launch_bounds__(128)
void agg_kernel(const __half* __restrict__ h, const float* __restrict__ norm,
                const int* __restrict__ off, const int* __restrict__ csr,
                __half* __restrict__ F)
{
    int node = blockIdx.x;
    int c    = threadIdx.x * 4;
    int s0 = __ldg(off + node);
    int s1 = __ldg(off + node + 1);
    float4 acc = make_float4(0.f, 0.f, 0.f, 0.f);
    int j = s0;
    for (; j + 3 < s1; j += 4) {
        int   si[4];
        float wi[4];
        #pragma unroll
        for (int u = 0; u < 4; u++) si[u] = __ldg(csr + j + u);
        #pragma unroll
        for (int u = 0; u < 4; u++) wi[u] = __ldg(norm + si[u]);
        uint2 q[4];
        #pragma unroll
        for (int u = 0; u < 4; u++)
            q[u] = *reinterpret_cast<const uint2*>(h + (size_t)si[u] * D + c);
        #pragma unroll
        for (int u = 0; u < 4; u++) {
            float2 lo = __half22float2(*reinterpret_cast<__half2*>(&q[u].x));
            float2 hi = __half22float2(*reinterpret_cast<__half2*>(&q[u].y));
            acc.x += wi[u] * lo.x;
            acc.y += wi[u] * lo.y;
            acc.z += wi[u] * hi.x;
            acc.w += wi[u] * hi.y;
        }
    }
    for (; j < s1; j++) {
        int sA = __ldg(csr + j);
        float wA = __ldg(norm + sA);
        uint2 q = *reinterpret_cast<const uint2*>(h + (size_t)sA * D + c);
        float2 lo = __half22float2(*reinterpret_cast<__half2*>(&q.x));
        float2 hi = __half22float2(*reinterpret_cast<__half2*>(&q.y));
        acc.x += wA * lo.x; acc.y += wA * lo.y;
        acc.z += wA * hi.x; acc.w += wA * hi.y;
    }
    float wn = __ldg(norm + node) * 0.9f;
    __half2 lo = __floats2half2_rn(acc.x * wn, acc.y * wn);
    __half2 hi = __floats2half2_rn(acc.z * wn, acc.w * wn);
    uint2 o;
    o.x = *reinterpret_cast<uint32_t*>(&lo);
    o.y = *reinterpret_cast<uint32_t*>(&hi);
    *reinterpret_cast<uint2*>(F + (size_t)node * D + c) = o;
}

// ================= unified fp16 GEMM (cp.async + ldmatrix, m16n8k16) =========
// SMEM tiles: 128 rows x 32 halves, row stride 80 B.
#define STG 3
#define TB16 10240

// LAYER=false: out16 = half(A0@B0^T + bias)                       (T=16)
// LAYER=true:  relu(beta*(A0@B0 + A1@B1) + (1-beta)*(A0+0.1*A1) + bias) (T=32)
template <bool LAYER, bool OUT32>
__global__ __launch_bounds__(256, 2)
void gemm16(const __half* __restrict__ A0, const __half* __restrict__ A1,
            const __half* __restrict__ B0, const __half* __restrict__ B1,
            const float* __restrict__ bias, float* __restrict__ C,
            __half* __restrict__ C16, int M, float beta)
{
    extern __shared__ unsigned sm[];
    const int tid = threadIdx.x, lane = tid & 31, warp = tid >> 5;
    const int wm = warp >> 2, wn = warp & 3;
    const int bm = blockIdx.y * 128, bn = blockIdx.x * 128;
    const uint32_t smb  = (uint32_t)__cvta_generic_to_shared(sm);
    const uint32_t smbB = smb + STG * TB16;

    float acc[4][4][4] = {};

    int lrow[2], lch[2], avalid[2];
    uint32_t dA[2], dB[2];
    #pragma unroll
    for (int i = 0; i < 2; i++) {
        int cid = tid + i * 256;
        lrow[i] = cid >> 2;
        lch[i]  = cid & 3;
        dA[i] = smb  + (uint32_t)(lrow[i] * 80 + lch[i] * 16);
        dB[i] = smbB + (uint32_t)(lrow[i] * 80 + lch[i] * 16);
        avalid[i] = (bm + lrow[i] < M) ? 16 : 0;
    }

    auto issue = [&](int stage, int t) {
        const __half* Ap;
        const __half* Bp;
        int k0;
        if (LAYER) {
            bool second = (t >= 16);
            Ap = second ? A1 : A0;
            Bp = second ? B1 : B0;
            k0 = (t & 15) * 32;
        } else {
            Ap = A0; Bp = B0; k0 = t * 32;
        }
        uint32_t so = (uint32_t)stage * TB16;
        #pragma unroll
        for (int i = 0; i < 2; i++) {
            const __half* as = Ap + (size_t)(avalid[i] ? bm + lrow[i] : 0) * D + k0 + lch[i] * 8;
            cp16(dA[i] + so, as, avalid[i]);
            const __half* bs = Bp + (size_t)(bn + lrow[i]) * D + k0 + lch[i] * 8;
            cp16(dB[i] + so, bs, 16);
        }
        cp_commit();
    };

    uint32_t aoff[4];
    #pragma unroll
    for (int mt = 0; mt < 4; mt++) {
        int row = wm * 64 + mt * 16 + (lane & 15);
        aoff[mt] = (uint32_t)(row * 80 + ((lane >> 4) & 1) * 16);
    }
    uint32_t boff[2];
    #pragma unroll
    for (int np = 0; np < 2; np++) {
        int row = wn * 32 + np * 16 + (lane & 7) + ((lane & 16) ? 8 : 0);
        boff[np] = (uint32_t)(row * 80 + ((lane >> 3) & 1) * 16);
    }

    auto compute = [&](int stage) {
        uint32_t sa = smb  + (uint32_t)stage * TB16;
        uint32_t sb = smbB + (uint32_t)stage * TB16;
        #pragma unroll
        for (int kc = 0; kc < 2; kc++) {
            unsigned af[4][4], bf[4][2];
            #pragma unroll
            for (int mt = 0; mt < 4; mt++)
                ldsm4(af[mt][0], af[mt][1], af[mt][2], af[mt][3],
                      sa + aoff[mt] + kc * 32);
            #pragma unroll
            for (int np = 0; np < 2; np++)
                ldsm4(bf[2 * np][0], bf[2 * np][1], bf[2 * np + 1][0], bf[2 * np + 1][1],
                      sb + boff[np] + kc * 32);
            #pragma unroll
            for (int mt = 0; mt < 4; mt++)
                #pragma unroll
                for (int nt = 0; nt < 4; nt++)
                    mma16(acc[mt][nt], af[mt][0], af[mt][1], af[mt][2], af[mt][3],
                          bf[nt][0], bf[nt][1]);
        }
    };

    const int T = LAYER ? 32 : 16;
    issue(0, 0);
    issue(1, 1);
    for (int t = 0; t < T; t++) {
        cp_wait<STG - 2>();
        __syncthreads();
        if (t + STG - 1 < T) issue((t + STG - 1) % STG, t + STG - 1);
        else                 cp_commit();
        compute(t % STG);
    }

    const int grp = lane >> 2, tig = lane & 3;
    const float ob = 1.0f - beta;
    #pragma unroll
    for (int mt = 0; mt < 4; mt++) {
        int gr[2];
        gr[0] = bm + wm * 64 + mt * 16 + grp;
        gr[1] = gr[0] + 8;
        #pragma unroll
        for (int nt = 0; nt < 4; nt++) {
            int gc = bn + wn * 32 + nt * 8 + tig * 2;
            float2 bb = *reinterpret_cast<const float2*>(bias + gc);
            #pragma unroll
            for (int hh = 0; hh < 2; hh++) {
                if (gr[hh] >= M) continue;
                size_t base = (size_t)gr[hh] * D + gc;
                float2 v;
                if (LAYER) {
                    float2 f  = __half22float2(*reinterpret_cast<const __half2*>(A0 + base));
                    float2 h0 = __half22float2(*reinterpret_cast<const __half2*>(A1 + base));
                    v.x = fmaxf(beta * acc[mt][nt][2 * hh + 0] + ob * (f.x + 0.1f * h0.x) + bb.x, 0.f);
                    v.y = fmaxf(beta * acc[mt][nt][2 * hh + 1] + ob * (f.y + 0.1f * h0.y) + bb.y, 0.f);
                } else {
                    v.x = acc[mt][nt][2 * hh + 0] + bb.x;
                    v.y = acc[mt][nt][2 * hh + 1] + bb.y;
                }
                if (OUT32)
                    *reinterpret_cast<float2*>(C + base) = v;
                else
                    *reinterpret_cast<__half2*>(C16 + base) = __floats2half2_rn(v.x, v.y);
            }
        }
    }
}

// ================= host orchestration =========================================
extern "C" void kernel_launch(void* const* d_in, const int* in_sizes, int n_in,
                              void* d_out, int out_size)
{
    const float* feat = (const float*)d_in[0];
    const int*   src  = (const int*)  d_in[1];
    const int*   dst  = (const int*)  d_in[2];
    const float* fc_w = (const float*)d_in[3];
    const float* fc_b = (const float*)d_in[4];
    const float* w1_1 = (const float*)d_in[5];
    const float* w2_1 = (const float*)d_in[6];
    const float* b_1  = (const float*)d_in[7];
    const float* w1_2 = (const float*)d_in[8];
    const float* w2_2 = (const float*)d_in[9];
    const float* b_2  = (const float*)d_in[10];
    float* out = (float*)d_out;

    int M = in_sizes[0] / D;
    int E = in_sizes[1];

    float *NORM;
    __half *H16, *R16, *F16, *FT16, *W16;
    int *CNT, *OFF, *CUR, *CSR;
    cudaGetSymbolAddress((void**)&H16,  g_H16);
    cudaGetSymbolAddress((void**)&R16,  g_R16);
    cudaGetSymbolAddress((void**)&F16,  g_F16);
    cudaGetSymbolAddress((void**)&FT16, g_FT16);
    cudaGetSymbolAddress((void**)&W16,  g_W16);
    cudaGetSymbolAddress((void**)&NORM, g_norm);
    cudaGetSymbolAddress((void**)&CNT,  g_cnt);
    cudaGetSymbolAddress((void**)&OFF,  g_off);
    cudaGetSymbolAddress((void**)&CUR,  g_cur);
    cudaGetSymbolAddress((void**)&CSR,  g_csr);

    const int smem = STG * TB16 * 2;       // 61440
    cudaFuncSetAttribute((const void*)gemm16<false, false>, cudaFuncAttributeMaxDynamicSharedMemorySize, smem);
    cudaFuncSetAttribute((const void*)gemm16<true,  false>, cudaFuncAttributeMaxDynamicSharedMemorySize, smem);
    cudaFuncSetAttribute((const void*)gemm16<true,  true >, cudaFuncAttributeMaxDynamicSharedMemorySize, smem);

    dim3 grid(D / 128, (M + 127) / 128);

    int featN = M * D;
    int nbd = (E + 255) / 256;
    int nbf = (featN + 2047) / 2048;
    int nb_total = nbd + nbf + 128 + 1024;

    prep_all<<<nb_total, 256>>>(dst, CNT, E, nbd,
                                feat, FT16, featN, nbf,
                                fc_w, w1_1, w2_1, w1_2, w2_2, W16);
    scan_kernel<<<1, 1024>>>(CNT, OFF, CUR, NORM, M);

    gemm16<false, false><<<grid, 256, smem>>>(FT16, nullptr, W16, nullptr,
                                              fc_b, nullptr, H16, M, 0.f);

    fill_kernel<<<(E + 255) / 256, 256>>>(src, dst, CUR, CSR, E);

    const float beta1 = logf(2.0f);
    const float beta2 = logf(1.5f);

    agg_kernel<<<M, 128>>>(H16, NORM, OFF, CSR, F16);
    gemm16<true, false><<<grid, 256, smem>>>(F16, H16, W16 + 1 * D * D, W16 + 2 * D * D,
                                             b_1, nullptr, R16, M, beta1);

    agg_kernel<<<M, 128>>>(R16, NORM, OFF, CSR, F16);
    gemm16<true, true><<<grid, 256, smem>>>(F16, H16, W16 + 3 * D * D, W16 + 4 * D * D,
                                            b_2, out, nullptr, M, beta2);
}

// round 14
// speedup vs baseline: 1.4652x; 1.0688x over previous
#include <cuda_runtime.h>
#include <cuda_fp16.h>
#include <cstdint>
#include <math.h>

#define NMAX 20000
#define EMAX 320000
#define D 512

// ---------------- scratch (static device globals; no allocation) -------------
__device__ __half g_H16 [NMAX * D];
__device__ __half g_R16 [NMAX * D];
__device__ __half g_F16 [NMAX * D];
__device__ __half g_FT16[NMAX * D];      // feat in fp16
// fp16 weights [N][K]: fc, W1'(l1), W2'(l1), W1'(l2), W2'(l2)  (residual folded)
__device__ __half g_W16 [5 * D * D];
__device__ float  g_norm[NMAX];
__device__ int    g_cnt [NMAX];          // zero-init; scan re-zeroes each call
__device__ int    g_off [NMAX + 1];
__device__ int    g_cur [NMAX + 1];
__device__ int    g_csr [EMAX];

// ================= small helpers ==============================================
__device__ __forceinline__ void cp16(uint32_t dst, const void* src, int bytes)
{
    asm volatile("cp.async.cg.shared.global [%0], [%1], 16, %2;"
                 :: "r"(dst), "l"(src), "r"(bytes));
}
__device__ __forceinline__ void cp_commit() { asm volatile("cp.async.commit_group;"); }
template <int N> __device__ __forceinline__ void cp_wait()
{ asm volatile("cp.async.wait_group %0;" :: "n"(N)); }

__device__ __forceinline__ void mma16(float* c,
                                      unsigned a0, unsigned a1, unsigned a2, unsigned a3,
                                      unsigned b0, unsigned b1)
{
    asm volatile(
        "mma.sync.aligned.m16n8k16.row.col.f32.f16.f16.f32 "
        "{%0,%1,%2,%3},{%4,%5,%6,%7},{%8,%9},{%0,%1,%2,%3};"
        : "+f"(c[0]), "+f"(c[1]), "+f"(c[2]), "+f"(c[3])
        : "r"(a0), "r"(a1), "r"(a2), "r"(a3), "r"(b0), "r"(b1));
}

__device__ __forceinline__ void ldsm4(unsigned& r0, unsigned& r1, unsigned& r2, unsigned& r3,
                                      uint32_t addr)
{
    asm volatile("ldmatrix.sync.aligned.m8n8.x4.shared.b16 {%0,%1,%2,%3}, [%4];"
                 : "=r"(r0), "=r"(r1), "=r"(r2), "=r"(r3) : "r"(addr));
}

// ================= fused prep =================================================
// deg histogram | feat->fp16 | fcw->fp16 | layer weights: transpose + fold
// W1' = beta*W1 + (1-beta)*I ;  W2' = 0.1*(beta*W2 + (1-beta)*I)
__global__ __launch_bounds__(256)
void prep_all(const int* __restrict__ dst, int* __restrict__ cnt, int E, int nbd,
              const float* __restrict__ feat, __half* __restrict__ f16, int featN, int nbf,
              const float* __restrict__ fcw,
              const float* __restrict__ w11, const float* __restrict__ w21,
              const float* __restrict__ w12, const float* __restrict__ w22,
              __half* __restrict__ w16)
{
    __shared__ float tile[32][33];
    const int b = blockIdx.x, tid = threadIdx.x;

    if (b < nbd) {                                   // degree histogram
        int i = b * 256 + tid;
        if (i < E) atomicAdd(cnt + __ldg(dst + i), 1);
        return;
    }
    if (b < nbd + nbf) {                             // feat -> fp16
        int i = (b - nbd) * 2048 + tid * 8;
        if (i + 8 <= featN) {
            float4 a = *reinterpret_cast<const float4*>(feat + i);
            float4 c = *reinterpret_cast<const float4*>(feat + i + 4);
            __half2 h0 = __floats2half2_rn(a.x, a.y);
            __half2 h1 = __floats2half2_rn(a.z, a.w);
            __half2 h2 = __floats2half2_rn(c.x, c.y);
            __half2 h3 = __floats2half2_rn(c.z, c.w);
            uint4 o;
            o.x = *reinterpret_cast<uint32_t*>(&h0);
            o.y = *reinterpret_cast<uint32_t*>(&h1);
            o.z = *reinterpret_cast<uint32_t*>(&h2);
            o.w = *reinterpret_cast<uint32_t*>(&h3);
            *reinterpret_cast<uint4*>(f16 + i) = o;
        }
        return;
    }
    if (b < nbd + nbf + 128) {                       // fc_w -> fp16 (already [N][K])
        int i = (b - nbd - nbf) * 2048 + tid * 8;
        float4 a = *reinterpret_cast<const float4*>(fcw + i);
        float4 c = *reinterpret_cast<const float4*>(fcw + i + 4);
        __half2 h0 = __floats2half2_rn(a.x, a.y);
        __half2 h1 = __floats2half2_rn(a.z, a.w);
        __half2 h2 = __floats2half2_rn(c.x, c.y);
        __half2 h3 = __floats2half2_rn(c.z, c.w);
        uint4 o;
        o.x = *reinterpret_cast<uint32_t*>(&h0);
        o.y = *reinterpret_cast<uint32_t*>(&h1);
        o.z = *reinterpret_cast<uint32_t*>(&h2);
        o.w = *reinterpret_cast<uint32_t*>(&h3);
        *reinterpret_cast<uint4*>(w16 + i) = o;
        return;
    }
    // layer weights [K][N] -> [N][K] fp16, residual folded
    const float beta1 = 0.69314718056f;   // log(2)
    const float beta2 = 0.40546510811f;   // log(1.5)
    int b2  = b - nbd - nbf - 128;
    int mat = b2 >> 8;
    int rem = b2 & 255;
    int n0 = (rem & 15) * 32, k0 = (rem >> 4) * 32;
    int tx = tid & 31, ty = tid >> 5;
    const float* s;
    float bsc, idadd;
    if      (mat == 0) { s = w11; bsc = beta1;        idadd = 1.0f - beta1; }
    else if (mat == 1) { s = w21; bsc = 0.1f * beta1; idadd = 0.1f * (1.0f - beta1); }
    else if (mat == 2) { s = w12; bsc = beta2;        idadd = 1.0f - beta2; }
    else               { s = w22; bsc = 0.1f * beta2; idadd = 0.1f * (1.0f - beta2); }
    __half* dstw = w16 + (size_t)(mat + 1) * D * D;
    #pragma unroll
    for (int j = 0; j < 4; j++)
        tile[ty + j * 8][tx] = s[(size_t)(k0 + ty + j * 8) * D + n0 + tx];
    __syncthreads();
    #pragma unroll
    for (int j = 0; j < 4; j++) {
        int nn = n0 + ty + j * 8;
        int kk = k0 + tx;
        float v = tile[tx][ty + j * 8] * bsc + ((nn == kk) ? idadd : 0.0f);
        dstw[(size_t)nn * D + kk] = __float2half(v);
    }
}

// ================= scan: prefix + cur + norm + cnt re-zero ====================
__global__ void scan_kernel(int* __restrict__ cnt, int* __restrict__ off,
                            int* __restrict__ cur, float* __restrict__ norm, int n)
{
    __shared__ int sh[1024];
    const int CH = 20;
    int t = threadIdx.x;
    int base = t * CH;
    int v[CH];
    if (base + CH <= n) {
        #pragma unroll
        for (int i = 0; i < CH / 4; i++) {
            int4 q = *reinterpret_cast<const int4*>(cnt + base + i * 4);
            v[i * 4 + 0] = q.x; v[i * 4 + 1] = q.y;
            v[i * 4 + 2] = q.z; v[i * 4 + 3] = q.w;
        }
    } else {
        #pragma unroll
        for (int i = 0; i < CH; i++) v[i] = (base + i < n) ? cnt[base + i] : 0;
    }
    int s = 0;
    #pragma unroll
    for (int i = 0; i < CH; i++) s += v[i];
    sh[t] = s;
    __syncthreads();
    for (int d = 1; d < 1024; d <<= 1) {
        int x = (t >= d) ? sh[t - d] : 0;
        __syncthreads();
        sh[t] += x;
        __syncthreads();
    }
    int run = sh[t] - s;
    int offv[CH];
    float nv[CH];
    #pragma unroll
    for (int i = 0; i < CH; i++) {
        offv[i] = run;
        nv[i]   = rsqrtf(fmaxf((float)v[i], 1.0f));
        run += v[i];
    }
    if (base + CH <= n) {
        #pragma unroll
        for (int i = 0; i < CH; i += 4) {
            int4 o = make_int4(offv[i], offv[i + 1], offv[i + 2], offv[i + 3]);
            *reinterpret_cast<int4*>(off + base + i) = o;
            *reinterpret_cast<int4*>(cur + base + i) = o;
            *reinterpret_cast<float4*>(norm + base + i) =
                make_float4(nv[i], nv[i + 1], nv[i + 2], nv[i + 3]);
            *reinterpret_cast<int4*>(cnt + base + i) = make_int4(0, 0, 0, 0);
        }
    } else {
        for (int i = 0; i < CH; i++) {
            int idx = base + i;
            if (idx < n) {
                off[idx] = offv[i]; cur[idx] = offv[i]; norm[idx] = nv[i];
                cnt[idx] = 0;
            }
        }
    }
    if (t == 1023) off[n] = sh[1023];
}

__global__ void fill_kernel(const int* __restrict__ src, const int* __restrict__ dst,
                            int* __restrict__ cur, int* __restrict__ csr, int E)
{
    int i = blockIdx.x * blockDim.x + threadIdx.x;
    if (i < E) {
        int d = __ldg(dst + i);
        int p = atomicAdd(cur + d, 1);
        csr[p] = __ldg(src + i);
    }
}

// ================= aggregation: fp16 gather -> fp16 out ======================
__global__ __launch_bounds__(128)
void agg_kernel(const __half* __restrict__ h, const float* __restrict__ norm,
                const int* __restrict__ off, const int* __restrict__ csr,
                __half* __restrict__ F)
{
    int node = blockIdx.x;
    int c    = threadIdx.x * 4;
    int s0 = __ldg(off + node);
    int s1 = __ldg(off + node + 1);
    float4 acc = make_float4(0.f, 0.f, 0.f, 0.f);
    int j = s0;
    for (; j + 3 < s1; j += 4) {
        int   si[4];
        float wi[4];
        #pragma unroll
        for (int u = 0; u < 4; u++) si[u] = __ldg(csr + j + u);
        #pragma unroll
        for (int u = 0; u < 4; u++) wi[u] = __ldg(norm + si[u]);
        uint2 q[4];
        #pragma unroll
        for (int u = 0; u < 4; u++)
            q[u] = *reinterpret_cast<const uint2*>(h + (size_t)si[u] * D + c);
        #pragma unroll
        for (int u = 0; u < 4; u++) {
            float2 lo = __half22float2(*reinterpret_cast<__half2*>(&q[u].x));
            float2 hi = __half22float2(*reinterpret_cast<__half2*>(&q[u].y));
            acc.x += wi[u] * lo.x;
            acc.y += wi[u] * lo.y;
            acc.z += wi[u] * hi.x;
            acc.w += wi[u] * hi.y;
        }
    }
    for (; j < s1; j++) {
        int sA = __ldg(csr + j);
        float wA = __ldg(norm + sA);
        uint2 q = *reinterpret_cast<const uint2*>(h + (size_t)sA * D + c);
        float2 lo = __half22float2(*reinterpret_cast<__half2*>(&q.x));
        float2 hi = __half22float2(*reinterpret_cast<__half2*>(&q.y));
        acc.x += wA * lo.x; acc.y += wA * lo.y;
        acc.z += wA * hi.x; acc.w += wA * hi.y;
    }
    float wn = __ldg(norm + node) * 0.9f;
    __half2 lo = __floats2half2_rn(acc.x * wn, acc.y * wn);
    __half2 hi = __floats2half2_rn(acc.z * wn, acc.w * wn);
    uint2 o;
    o.x = *reinterpret_cast<uint32_t*>(&lo);
    o.y = *reinterpret_cast<uint32_t*>(&hi);
    *reinterpret_cast<uint2*>(F + (size_t)node * D + c) = o;
}

// ================= unified fp16 GEMM (cp.async + ldmatrix, m16n8k16) =========
// SMEM tiles: 128 rows x 32 halves, row stride 80 B. 4-stage pipeline.
#define STG 4
#define TB16 10240

// LAYER=false: out16 = half(A0@B0^T + bias)                (T=16)
// LAYER=true:  out = relu(A0@B0' + A1@B1' + bias)          (T=32, weights folded)
template <bool LAYER, bool OUT32>
__global__ __launch_bounds__(256, 2)
void gemm16(const __half* __restrict__ A0, const __half* __restrict__ A1,
            const __half* __restrict__ B0, const __half* __restrict__ B1,
            const float* __restrict__ bias, float* __restrict__ C,
            __half* __restrict__ C16, int M)
{
    extern __shared__ unsigned sm[];
    const int tid = threadIdx.x, lane = tid & 31, warp = tid >> 5;
    const int wm = warp >> 2, wn = warp & 3;
    const int bm = blockIdx.y * 128, bn = blockIdx.x * 128;
    const uint32_t smb  = (uint32_t)__cvta_generic_to_shared(sm);
    const uint32_t smbB = smb + STG * TB16;

    float acc[4][4][4] = {};

    int lrow[2], lch[2], avalid[2];
    uint32_t dA[2], dB[2];
    #pragma unroll
    for (int i = 0; i < 2; i++) {
        int cid = tid + i * 256;
        lrow[i] = cid >> 2;
        lch[i]  = cid & 3;
        dA[i] = smb  + (uint32_t)(lrow[i] * 80 + lch[i] * 16);
        dB[i] = smbB + (uint32_t)(lrow[i] * 80 + lch[i] * 16);
        avalid[i] = (bm + lrow[i] < M) ? 16 : 0;
    }

    auto issue = [&](int stage, int t) {
        const __half* Ap;
        const __half* Bp;
        int k0;
        if (LAYER) {
            bool second = (t >= 16);
            Ap = second ? A1 : A0;
            Bp = second ? B1 : B0;
            k0 = (t & 15) * 32;
        } else {
            Ap = A0; Bp = B0; k0 = t * 32;
        }
        uint32_t so = (uint32_t)stage * TB16;
        #pragma unroll
        for (int i = 0; i < 2; i++) {
            const __half* as = Ap + (size_t)(avalid[i] ? bm + lrow[i] : 0) * D + k0 + lch[i] * 8;
            cp16(dA[i] + so, as, avalid[i]);
            const __half* bs = Bp + (size_t)(bn + lrow[i]) * D + k0 + lch[i] * 8;
            cp16(dB[i] + so, bs, 16);
        }
        cp_commit();
    };

    uint32_t aoff[4];
    #pragma unroll
    for (int mt = 0; mt < 4; mt++) {
        int row = wm * 64 + mt * 16 + (lane & 15);
        aoff[mt] = (uint32_t)(row * 80 + ((lane >> 4) & 1) * 16);
    }
    uint32_t boff[2];
    #pragma unroll
    for (int np = 0; np < 2; np++) {
        int row = wn * 32 + np * 16 + (lane & 7) + ((lane & 16) ? 8 : 0);
        boff[np] = (uint32_t)(row * 80 + ((lane >> 3) & 1) * 16);
    }

    auto compute = [&](int stage) {
        uint32_t sa = smb  + (uint32_t)stage * TB16;
        uint32_t sb = smbB + (uint32_t)stage * TB16;
        #pragma unroll
        for (int kc = 0; kc < 2; kc++) {
            unsigned af[4][4], bf[4][2];
            #pragma unroll
            for (int mt = 0; mt < 4; mt++)
                ldsm4(af[mt][0], af[mt][1], af[mt][2], af[mt][3],
                      sa + aoff[mt] + kc * 32);
            #pragma unroll
            for (int np = 0; np < 2; np++)
                ldsm4(bf[2 * np][0], bf[2 * np][1], bf[2 * np + 1][0], bf[2 * np + 1][1],
                      sb + boff[np] + kc * 32);
            #pragma unroll
            for (int mt = 0; mt < 4; mt++)
                #pragma unroll
                for (int nt = 0; nt < 4; nt++)
                    mma16(acc[mt][nt], af[mt][0], af[mt][1], af[mt][2], af[mt][3],
                          bf[nt][0], bf[nt][1]);
        }
    };

    const int T = LAYER ? 32 : 16;
    #pragma unroll
    for (int p = 0; p < STG - 1; p++) issue(p, p);
    for (int t = 0; t < T; t++) {
        cp_wait<STG - 2>();
        __syncthreads();
        if (t + STG - 1 < T) issue((t + STG - 1) % STG, t + STG - 1);
        else                 cp_commit();
        compute(t % STG);
    }

    const int grp = lane >> 2, tig = lane & 3;
    #pragma unroll
    for (int mt = 0; mt < 4; mt++) {
        int gr[2];
        gr[0] = bm + wm * 64 + mt * 16 + grp;
        gr[1] = gr[0] + 8;
        #pragma unroll
        for (int nt = 0; nt < 4; nt++) {
            int gc = bn + wn * 32 + nt * 8 + tig * 2;
            float2 bb = *reinterpret_cast<const float2*>(bias + gc);
            #pragma unroll
            for (int hh = 0; hh < 2; hh++) {
                if (gr[hh] >= M) continue;
                size_t base = (size_t)gr[hh] * D + gc;
                float2 v;
                v.x = acc[mt][nt][2 * hh + 0] + bb.x;
                v.y = acc[mt][nt][2 * hh + 1] + bb.y;
                if (LAYER) {
                    v.x = fmaxf(v.x, 0.f);
                    v.y = fmaxf(v.y, 0.f);
                }
                if (OUT32)
                    *reinterpret_cast<float2*>(C + base) = v;
                else
                    *reinterpret_cast<__half2*>(C16 + base) = __floats2half2_rn(v.x, v.y);
            }
        }
    }
}

// ================= host orchestration =========================================
extern "C" void kernel_launch(void* const* d_in, const int* in_sizes, int n_in,
                              void* d_out, int out_size)
{
    const float* feat = (const float*)d_in[0];
    const int*   src  = (const int*)  d_in[1];
    const int*   dst  = (const int*)  d_in[2];
    const float* fc_w = (const float*)d_in[3];
    const float* fc_b = (const float*)d_in[4];
    const float* w1_1 = (const float*)d_in[5];
    const float* w2_1 = (const float*)d_in[6];
    const float* b_1  = (const float*)d_in[7];
    const float* w1_2 = (const float*)d_in[8];
    const float* w2_2 = (const float*)d_in[9];
    const float* b_2  = (const float*)d_in[10];
    float* out = (float*)d_out;

    int M = in_sizes[0] / D;
    int E = in_sizes[1];

    float *NORM;
    __half *H16, *R16, *F16, *FT16, *W16;
    int *CNT, *OFF, *CUR, *CSR;
    cudaGetSymbolAddress((void**)&H16,  g_H16);
    cudaGetSymbolAddress((void**)&R16,  g_R16);
    cudaGetSymbolAddress((void**)&F16,  g_F16);
    cudaGetSymbolAddress((void**)&FT16, g_FT16);
    cudaGetSymbolAddress((void**)&W16,  g_W16);
    cudaGetSymbolAddress((void**)&NORM, g_norm);
    cudaGetSymbolAddress((void**)&CNT,  g_cnt);
    cudaGetSymbolAddress((void**)&OFF,  g_off);
    cudaGetSymbolAddress((void**)&CUR,  g_cur);
    cudaGetSymbolAddress((void**)&CSR,  g_csr);

    const int smem = STG * TB16 * 2;       // 81920
    cudaFuncSetAttribute((const void*)gemm16<false, false>, cudaFuncAttributeMaxDynamicSharedMemorySize, smem);
    cudaFuncSetAttribute((const void*)gemm16<true,  false>, cudaFuncAttributeMaxDynamicSharedMemorySize, smem);
    cudaFuncSetAttribute((const void*)gemm16<true,  true >, cudaFuncAttributeMaxDynamicSharedMemorySize, smem);

    dim3 grid(D / 128, (M + 127) / 128);

    int featN = M * D;
    int nbd = (E + 255) / 256;
    int nbf = (featN + 2047) / 2048;
    int nb_total = nbd + nbf + 128 + 1024;

    prep_all<<<nb_total, 256>>>(dst, CNT, E, nbd,
                                feat, FT16, featN, nbf,
                                fc_w, w1_1, w2_1, w1_2, w2_2, W16);
    scan_kernel<<<1, 1024>>>(CNT, OFF, CUR, NORM, M);

    gemm16<false, false><<<grid, 256, smem>>>(FT16, nullptr, W16, nullptr,
                                              fc_b, nullptr, H16, M);

    fill_kernel<<<(E + 255) / 256, 256>>>(src, dst, CUR, CSR, E);

    agg_kernel<<<M, 128>>>(H16, NORM, OFF, CSR, F16);
    gemm16<true, false><<<grid, 256, smem>>>(F16, H16, W16 + 1 * D * D, W16 + 2 * D * D,
                                             b_1, nullptr, R16, M);

    agg_kernel<<<M, 128>>>(R16, NORM, OFF, CSR, F16);
    gemm16<true, true><<<grid, 256, smem>>>(F16, H16, W16 + 3 * D * D, W16 + 4 * D * D,
                                            b_2, out, nullptr, M);
}